// round 8
// baseline (speedup 1.0000x reference)
#include <cuda_runtime.h>
#include <math.h>

constexpr int N_OSC  = 2048;
constexpr int N_SAMP = 16384;
constexpr int LAT    = 32;
constexpr int HALF   = N_OSC * LAT;               // 65536

constexpr int OSC_CHUNK  = 32;
constexpr int SAMP_CHUNK = 2048;
constexpr int THREADS    = 256;
constexpr int SPT        = 8;                      // contiguous samples per thread
constexpr int N_OSC_BLK  = N_OSC / OSC_CHUNK;      // 64
constexpr int N_SAMP_BLK = N_SAMP / SAMP_CHUNK;    // 8

// Partial signals per oscillator block: 64 x 16384 floats = 4 MB
__device__ float g_scratch[N_OSC_BLK * N_SAMP];

// -----------------------------------------------------------------------------
// Main kernel. Block = 32 oscillators x 2048 samples, 256 threads.
// Grid = 8 x 64 = 512 blocks -> SINGLE WAVE at 4 blocks/SM (592 slots).
//
// NOTE (R7 lesson): outputs are error-checked SEPARATELY; the signal output
// cannot tolerate bf16 amp quantization (1.3e-3). All-fp32 tables here.
//
// Prologue (fp32 warp-scan, validated R5/R6): lane k owns breakpoint k.
// Main loop: Q = base + c1q*fp + c2q*df (pre-scaled by pi); MUFU sin;
// amp = ap + w*da. 4 FMA + 1 MUFU per (osc,sample); 2 broadcast LDS per osc
// amortized over 8 samples.
// -----------------------------------------------------------------------------
__global__ __launch_bounds__(THREADS, 4)
void osc_kernel(const float* __restrict__ latent) {
    __shared__ float4 s_pack[OSC_CHUNK * LAT];   // (fp, df, ap, da)  16 KB
    __shared__ float  s_base[OSC_CHUNK * LAT];   // pi*(C_k mod 2)     4 KB

    const int tid     = threadIdx.x;
    const int lane    = tid & 31;
    const int warp    = tid >> 5;
    const int oscBase = blockIdx.y * OSC_CHUNK;
    const float PI_F  = 3.14159265358979323846f;

    // ---- prologue: 8 warps x 4 oscillators ----
#pragma unroll
    for (int j = 0; j < OSC_CHUNK / 8; ++j) {
        const int o  = warp * (OSC_CHUNK / 8) + j;
        const int go = oscBase + o;
        const float f  = fabsf(latent[(size_t)(N_OSC + go) * LAT + lane]);
        const float a  = fabsf(latent[(size_t)go * LAT + lane]);
        const float fn = __shfl_down_sync(0xffffffffu, f, 1);
        const float an = __shfl_down_sync(0xffffffffu, a, 1);
        const float df = (lane < 31) ? (fn - f) : 0.0f;
        const float da = (lane < 31) ? (an - a) : 0.0f;
        const float t = (lane < 31) ? 256.0f * (f + fn) : 0.0f;
        float sc = t;
#pragma unroll
        for (int d = 1; d < 32; d <<= 1) {
            const float u = __shfl_up_sync(0xffffffffu, sc, d);
            if (lane >= d) sc += u;
        }
        const float f0 = __shfl_sync(0xffffffffu, f, 0);
        const float C  = fmaf(256.0f, f0, sc - t);        // exclusive prefix C_k
        const float r  = fmaf(-2.0f, rintf(0.5f * C), C); // C mod 2, exact
        s_pack[o * LAT + lane] = make_float4(f, df, a, da);
        s_base[o * LAT + lane] = PI_F * r;
    }
    __syncthreads();

    // ---- per-thread sample constants (pre-scaled by pi) ----
    const int i0 = blockIdx.x * SAMP_CHUNK + tid * SPT;
    int k;
    float c1q[SPT], c2q[SPT], w[SPT];
    if (i0 < 256) {
        k = 0;
#pragma unroll
        for (int s = 0; s < SPT; ++s) { c1q[s] = PI_F * (float)(i0 + s - 255); c2q[s] = 0.0f; w[s] = 0.0f; }
    } else if (i0 >= 16128) {
        k = 31;
#pragma unroll
        for (int s = 0; s < SPT; ++s) { c1q[s] = PI_F * (float)(i0 + s - 16127); c2q[s] = 0.0f; w[s] = 0.0f; }
    } else {
        k = (i0 - 256) >> 9;
        const int m0 = (i0 - 256) & 511;
#pragma unroll
        for (int s = 0; s < SPT; ++s) {
            const float mp1 = (float)(m0 + s + 1);
            c1q[s] = PI_F * mp1;
            c2q[s] = PI_F * mp1 * mp1 * (1.0f / 1024.0f);
            w[s]   = ((float)(m0 + s) + 0.5f) * (1.0f / 512.0f);
        }
    }

    // ---- main loop ----
    float acc[SPT] = {0.f, 0.f, 0.f, 0.f, 0.f, 0.f, 0.f, 0.f};
    const float4* pk = &s_pack[k];
    const float*  bk = &s_base[k];
#pragma unroll 4
    for (int o = 0; o < OSC_CHUNK; ++o) {
        const float4 p  = pk[o * LAT];                 // (fp, df, ap, da)
        const float  bq = bk[o * LAT];
#pragma unroll
        for (int s = 0; s < SPT; ++s) {
            const float Q   = fmaf(c2q[s], p.y, fmaf(c1q[s], p.x, bq));
            const float sv  = __sinf(Q);
            const float amp = fmaf(w[s], p.w, p.z);
            acc[s] = fmaf(sv, amp, acc[s]);
        }
    }

    float* dst = &g_scratch[blockIdx.y * N_SAMP + i0];
    *reinterpret_cast<float4*>(dst)     = make_float4(acc[0], acc[1], acc[2], acc[3]);
    *reinterpret_cast<float4*>(dst + 4) = make_float4(acc[4], acc[5], acc[6], acc[7]);
}

// -----------------------------------------------------------------------------
// Epilogue: signal = 16 threads per 4-sample group (4 rows each, float4 loads,
// 4-step shfl_xor butterfly); params = |latent| float4 passthrough.
// 98304 threads total = 384 blocks.
// -----------------------------------------------------------------------------
__global__ void epilogue_kernel(const float* __restrict__ latent, float* __restrict__ out) {
    const int t = blockIdx.x * blockDim.x + threadIdx.x;   // 0..98303
    if (t < N_SAMP * 4) {                                   // 65536 signal threads
        const int g   = t >> 4;                             // 4-sample group
        const int sub = t & 15;                             // row quartet
        const int i   = g * 4;
        float4 acc = make_float4(0.f, 0.f, 0.f, 0.f);
#pragma unroll
        for (int r = 0; r < 4; ++r) {
            const float4 v = *reinterpret_cast<const float4*>(
                &g_scratch[(sub * 4 + r) * N_SAMP + i]);
            acc.x += v.x; acc.y += v.y; acc.z += v.z; acc.w += v.w;
        }
#pragma unroll
        for (int d = 8; d >= 1; d >>= 1) {
            acc.x += __shfl_xor_sync(0xffffffffu, acc.x, d);
            acc.y += __shfl_xor_sync(0xffffffffu, acc.y, d);
            acc.z += __shfl_xor_sync(0xffffffffu, acc.z, d);
            acc.w += __shfl_xor_sync(0xffffffffu, acc.w, d);
        }
        if (sub == 0) {
            const float sc = 1.0f / (float)N_OSC;
            *reinterpret_cast<float4*>(&out[i]) =
                make_float4(acc.x * sc, acc.y * sc, acc.z * sc, acc.w * sc);
        }
    } else {                                                // 32768 param threads
        const int idx = (t - N_SAMP * 4) * 4;               // 0..131068
        const int src = (idx < HALF) ? (HALF + idx) : (idx - HALF);
        const float4 v = *reinterpret_cast<const float4*>(&latent[src]);
        *reinterpret_cast<float4*>(&out[N_SAMP + idx]) =
            make_float4(fabsf(v.x), fabsf(v.y), fabsf(v.z), fabsf(v.w));
    }
}

extern "C" void kernel_launch(void* const* d_in, const int* in_sizes, int n_in,
                              void* d_out, int out_size) {
    const float* latent = (const float*)d_in[n_in - 1];
    for (int i = 0; i < n_in; ++i) {
        if (in_sizes[i] == 2 * HALF) { latent = (const float*)d_in[i]; break; }
    }
    float* out = (float*)d_out;

    dim3 grid(N_SAMP_BLK, N_OSC_BLK);                       // 8 x 64 = 512 blocks
    osc_kernel<<<grid, THREADS>>>(latent);

    const int epi_threads = N_SAMP * 4 + 2 * HALF / 4;      // 98304
    epilogue_kernel<<<epi_threads / 256, 256>>>(latent, out);
}